// round 13
// baseline (speedup 1.0000x reference)
#include <cuda_runtime.h>
#include <cuda_bf16.h>

#define NB 2
#define NT 2048
#define NC 1024
#define NHD 16
#define HS 64
#define WINSZ 256
#define MR (NB * NT)   // 4096 rows

// ---------------- device-global scratch (allocation-free rule) --------------
__device__ __align__(256) __nv_bfloat16 g_xh[MR * NC], g_xl[MR * NC];
__device__ __align__(256) __nv_bfloat16 g_wah[3 * NC * NC], g_wal[3 * NC * NC]; // W_attn^T
__device__ __align__(256) __nv_bfloat16 g_wph[NC * NC], g_wpl[NC * NC];         // W_proj^T
__device__ __align__(256) __nv_bfloat16 g_yh[MR * NC], g_yl[MR * NC];
// attention operands, bf16 hi/lo, all [b,h,t,d] row-major
__device__ __align__(256) __nv_bfloat16 g_qh[MR * NC], g_ql[MR * NC];   // (pre-scaled 1/8)
__device__ __align__(256) __nv_bfloat16 g_kh[MR * NC], g_kl[MR * NC];
__device__ __align__(256) __nv_bfloat16 g_vh[MR * NC], g_vl[MR * NC];

// ---------------- helpers ---------------------------------------------------
__device__ __forceinline__ unsigned smem_u32(const void* p) {
    unsigned a;
    asm("{ .reg .u64 t; cvta.to.shared.u64 t, %1; cvt.u32.u64 %0, t; }"
        : "=r"(a) : "l"(p));
    return a;
}

__device__ __forceinline__ void ldsm4(unsigned& r0, unsigned& r1, unsigned& r2,
                                      unsigned& r3, unsigned addr) {
    asm volatile("ldmatrix.sync.aligned.m8n8.x4.shared.b16 {%0,%1,%2,%3}, [%4];"
                 : "=r"(r0), "=r"(r1), "=r"(r2), "=r"(r3) : "r"(addr));
}

__device__ __forceinline__ void ldsm4t(unsigned& r0, unsigned& r1, unsigned& r2,
                                       unsigned& r3, unsigned addr) {
    asm volatile("ldmatrix.sync.aligned.m8n8.x4.trans.shared.b16 {%0,%1,%2,%3}, [%4];"
                 : "=r"(r0), "=r"(r1), "=r"(r2), "=r"(r3) : "r"(addr));
}

__device__ __forceinline__ void mma16816(float* d, const unsigned* a, const unsigned* b) {
    asm volatile("mma.sync.aligned.m16n8k16.row.col.f32.bf16.bf16.f32 "
                 "{%0,%1,%2,%3}, {%4,%5,%6,%7}, {%8,%9}, {%0,%1,%2,%3};"
                 : "+f"(d[0]), "+f"(d[1]), "+f"(d[2]), "+f"(d[3])
                 : "r"(a[0]), "r"(a[1]), "r"(a[2]), "r"(a[3]),
                   "r"(b[0]), "r"(b[1]));
}

union Pack4 { __nv_bfloat16 b[4]; uint2 u; };
union PackB2 { __nv_bfloat162 v; unsigned u; };

__device__ __forceinline__ unsigned u32bf(__nv_bfloat162 x) {
    PackB2 p; p.v = x; return p.u;
}

__device__ __forceinline__ void split1(float v, __nv_bfloat16& h, __nv_bfloat16& l) {
    h = __float2bfloat16(v);
    l = __float2bfloat16(v - __bfloat162float(h));
}

__device__ __forceinline__ void split2(float a, float b, unsigned& hi, unsigned& lo) {
    __nv_bfloat162 h = __floats2bfloat162_rn(a, b);
    hi = u32bf(h);
    lo = u32bf(__floats2bfloat162_rn(a - __bfloat162float(h.x),
                                     b - __bfloat162float(h.y)));
}

// ---------------- prep kernels ----------------------------------------------
__global__ __launch_bounds__(256)
void splitx_kernel(const float4* __restrict__ x) {
    int i = blockIdx.x * 256 + threadIdx.x;
    float4 v = x[i];
    Pack4 h, l;
    split1(v.x, h.b[0], l.b[0]);
    split1(v.y, h.b[1], l.b[1]);
    split1(v.z, h.b[2], l.b[2]);
    split1(v.w, h.b[3], l.b[3]);
    ((uint2*)g_xh)[i] = h.u;
    ((uint2*)g_xl)[i] = l.u;
}

template<int NCOLS, int WHICH>
__global__ __launch_bounds__(256)
void tsplit_kernel(const float* __restrict__ W) {
    __shared__ float tile[32][33];
    __nv_bfloat16* Th = WHICH ? g_wph : g_wah;
    __nv_bfloat16* Tl = WHICH ? g_wpl : g_wal;
    const int tx = threadIdx.x, ty = threadIdx.y;
    const int j0 = blockIdx.x * 32;
    const int i0 = blockIdx.y * 32;
#pragma unroll
    for (int r = 0; r < 32; r += 8)
        tile[ty + r][tx] = W[(size_t)(i0 + ty + r) * NCOLS + j0 + tx];
    __syncthreads();
#pragma unroll
    for (int r = 0; r < 32; r += 8) {
        float v = tile[tx][ty + r];
        size_t o = (size_t)(j0 + ty + r) * NC + i0 + tx;
        __nv_bfloat16 h, l;
        split1(v, h, l);
        Th[o] = h;
        Tl[o] = l;
    }
}

// ---------------- split-bf16 HMMA GEMM --------------------------------------
// CTA tile 128(M) x 64(N), 4 warps along M. 4-stage pipeline, K-chunk 32,
// 64B rows SW64-swizzled, ONE __syncthreads per chunk. 96KB smem, 2 CTAs/SM.
#define STG_A    8192     // A tile: 128 rows x 64B
#define STG_B    4096     // B tile:  64 rows x 64B
#define STG_BYTES (2 * STG_A + 2 * STG_B)   // 24576
#define GEMM_SMEM (4 * STG_BYTES)           // 98304

struct Frag {
    unsigned ah[2][4], al[2][4];
    unsigned bh[16], bl[16];
};

template<int MODE>
__global__ __launch_bounds__(128, 2)
void hgemm(float* __restrict__ Cout) {
    extern __shared__ __align__(1024) char sm[];
    const unsigned sb = smem_u32(sm);
    const int tid = threadIdx.x;
    const int wm = tid >> 5, lane = tid & 31;
    const int col0 = blockIdx.x * 64;
    const int row0 = blockIdx.y * 128;

    const __nv_bfloat16* Ah = MODE ? g_yh : g_xh;
    const __nv_bfloat16* Al = MODE ? g_yl : g_xl;
    const __nv_bfloat16* Bh = MODE ? g_wph : g_wah;
    const __nv_bfloat16* Bl = MODE ? g_wpl : g_wal;

    const char* srcA[2];
    const char* srcB[2];
    srcA[0] = (const char*)Ah + (size_t)row0 * 2048;
    srcA[1] = (const char*)Al + (size_t)row0 * 2048;
    srcB[0] = (const char*)Bh + (size_t)col0 * 2048;
    srcB[1] = (const char*)Bl + (size_t)col0 * 2048;

    // chunk c covers K bytes [c*64, c*64+64)
    auto load_chunk = [&](int c, int buf) {
        const unsigned dst0 = sb + buf * STG_BYTES;
#pragma unroll
        for (int t = 0; t < 2; t++) {
#pragma unroll
            for (int i = 0; i < 4; i++) {
                const int unit = tid + i * 128;      // 0..511
                const int r = unit >> 2, cc = unit & 3;
                const unsigned bo = r * 64 + cc * 16;
                const unsigned sw = bo ^ ((bo >> 3) & 0x30);
                const char* s = srcA[t] + (size_t)r * 2048 + c * 64 + cc * 16;
                asm volatile("cp.async.cg.shared.global [%0], [%1], 16;"
                             :: "r"(dst0 + t * STG_A + sw), "l"(s) : "memory");
            }
        }
#pragma unroll
        for (int t = 0; t < 2; t++) {
#pragma unroll
            for (int i = 0; i < 2; i++) {
                const int unit = tid + i * 128;      // 0..255
                const int r = unit >> 2, cc = unit & 3;
                const unsigned bo = r * 64 + cc * 16;
                const unsigned sw = bo ^ ((bo >> 3) & 0x30);
                const char* s = srcB[t] + (size_t)r * 2048 + c * 64 + cc * 16;
                asm volatile("cp.async.cg.shared.global [%0], [%1], 16;"
                             :: "r"(dst0 + 2 * STG_A + t * STG_B + sw), "l"(s)
                             : "memory");
            }
        }
        asm volatile("cp.async.commit_group;" ::: "memory");
    };

    float acc[2][8][4];
#pragma unroll
    for (int mt = 0; mt < 2; mt++)
#pragma unroll
        for (int nt = 0; nt < 8; nt++)
#pragma unroll
            for (int e = 0; e < 4; e++) acc[mt][nt][e] = 0.f;

    const int arow_b = wm * 32 + (lane & 15);
    const int ahalf = lane >> 4;
    const int brow_b = ((lane >> 4) & 1) * 8 + (lane & 7);
    const int bhalf = (lane >> 3) & 1;

    Frag fr[2];

    // s in {0,1}: k16 substep within the 32-K chunk; granule = 2s+half in 0..3
    auto fetch = [&](int s, Frag& f, unsigned base) {
#pragma unroll
        for (int mt = 0; mt < 2; mt++) {
            const int row = arow_b + mt * 16;
            const unsigned off =
                row * 64 + (((2 * s + ahalf) ^ ((row >> 1) & 3)) * 16);
            ldsm4(f.ah[mt][0], f.ah[mt][1], f.ah[mt][2], f.ah[mt][3], base + off);
            ldsm4(f.al[mt][0], f.al[mt][1], f.al[mt][2], f.al[mt][3],
                  base + STG_A + off);
        }
#pragma unroll
        for (int j = 0; j < 4; j++) {
            const int row = brow_b + j * 16;
            const unsigned off =
                row * 64 + (((2 * s + bhalf) ^ ((row >> 1) & 3)) * 16);
            ldsm4(f.bh[4 * j], f.bh[4 * j + 1], f.bh[4 * j + 2], f.bh[4 * j + 3],
                  base + 2 * STG_A + off);
            ldsm4(f.bl[4 * j], f.bl[4 * j + 1], f.bl[4 * j + 2], f.bl[4 * j + 3],
                  base + 2 * STG_A + STG_B + off);
        }
    };

    auto compute = [&](Frag& f) {
#pragma unroll
        for (int mt = 0; mt < 2; mt++)
#pragma unroll
            for (int nt = 0; nt < 8; nt++) {
                mma16816(acc[mt][nt], f.ah[mt], &f.bh[nt * 2]);
                mma16816(acc[mt][nt], f.ah[mt], &f.bl[nt * 2]);
                mma16816(acc[mt][nt], f.al[mt], &f.bh[nt * 2]);
            }
    };

    load_chunk(0, 0);
    load_chunk(1, 1);
    load_chunk(2, 2);

    for (int c = 0; c < 32; c++) {
        asm volatile("cp.async.wait_group 2;" ::: "memory");
        __syncthreads();
        if (c + 3 < 32) load_chunk(c + 3, (c + 3) & 3);

        const unsigned base = sb + (c & 3) * STG_BYTES;
        fetch(0, fr[0], base);
        fetch(1, fr[1], base);
        compute(fr[0]);
        compute(fr[1]);
    }

    // -------- epilogue --------
    const int lm = lane >> 2;
    const int ln = (lane & 3) * 2;
#pragma unroll
    for (int mt = 0; mt < 2; mt++) {
        const int m0 = row0 + wm * 32 + mt * 16 + lm;
#pragma unroll
        for (int nt = 0; nt < 8; nt++) {
            const int gn = col0 + nt * 8 + ln;
            if (MODE == 0) {
                const int sect = gn >> 10;
                const int nn = gn & (NC - 1);
                const int hd = nn >> 6, dd = nn & 63;
#pragma unroll
                for (int half = 0; half < 2; half++) {
                    const int m = m0 + half * 8;
                    const int bb = m >> 11;
                    const int tt = m & (NT - 1);
                    float v0 = acc[mt][nt][2 * half];
                    float v1 = acc[mt][nt][2 * half + 1];
                    if (sect == 0) { v0 *= 0.125f; v1 *= 0.125f; }
                    unsigned hi, lo;
                    split2(v0, v1, hi, lo);
                    const size_t off =
                        ((size_t)(bb * NHD + hd) * NT + tt) * HS + dd;
                    if (sect == 0) {
                        *(unsigned*)&g_qh[off] = hi;
                        *(unsigned*)&g_ql[off] = lo;
                    } else if (sect == 1) {
                        *(unsigned*)&g_kh[off] = hi;
                        *(unsigned*)&g_kl[off] = lo;
                    } else {
                        *(unsigned*)&g_vh[off] = hi;
                        *(unsigned*)&g_vl[off] = lo;
                    }
                }
            } else {
#pragma unroll
                for (int half = 0; half < 2; half++) {
                    const int m = m0 + half * 8;
                    float* dst = Cout + (size_t)m * NC + gn;
                    *(float2*)dst = make_float2(acc[mt][nt][2 * half],
                                                acc[mt][nt][2 * half + 1]);
                }
            }
        }
    }
}

// ---------------- HMMA sliding-window flash attention ------------------------
// CTA: 64 queries x 1 head, 128 threads. V kept row-major; V^T fragments via
// ldmatrix.trans. Smem: Q hi/lo 16KB + double-buffered K/V hi/lo 2x32KB = 80KB.
#define ATTN_SMEM (16384 + 2 * 32768)

__global__ __launch_bounds__(128, 2)
void attn_mma() {
    extern __shared__ __align__(1024) char smraw[];
    const unsigned sb = smem_u32(smraw);
    const int tid = threadIdx.x;
    const int wm = tid >> 5, lane = tid & 31;
    const int qb = blockIdx.x * 64;
    const int h = blockIdx.y, b = blockIdx.z;

    const size_t bh = (size_t)(b * NHD + h);
    const __nv_bfloat16* Qhp = g_qh + (bh * NT + qb) * HS;
    const __nv_bfloat16* Qlp = g_ql + (bh * NT + qb) * HS;
    const __nv_bfloat16* Khp = g_kh + bh * NT * HS;
    const __nv_bfloat16* Klp = g_kl + bh * NT * HS;
    const __nv_bfloat16* Vhp = g_vh + bh * NT * HS;
    const __nv_bfloat16* Vlp = g_vl + bh * NT * HS;

    auto ld_tile = [&](unsigned dst, const __nv_bfloat16* src) {
#pragma unroll
        for (int i = 0; i < 4; i++) {
            const int unit = tid + i * 128;
            const int r = unit >> 3, cc = unit & 7;
            const unsigned d = dst + r * 128 + ((cc ^ (r & 7)) * 16);
            const char* s = (const char*)src + (size_t)r * 128 + cc * 16;
            asm volatile("cp.async.cg.shared.global [%0], [%1], 16;"
                         :: "r"(d), "l"(s) : "memory");
        }
    };

    auto kvload = [&](int kt, int buf) {
        const int kb = kt * 64;
        const unsigned kvb = sb + 16384 + buf * 32768;
        ld_tile(kvb,         Khp + (size_t)kb * HS);
        ld_tile(kvb + 8192,  Klp + (size_t)kb * HS);
        ld_tile(kvb + 16384, Vhp + (size_t)kb * HS);
        ld_tile(kvb + 24576, Vlp + (size_t)kb * HS);
        asm volatile("cp.async.commit_group;" ::: "memory");
    };

    const int tm = qb >> 6;
    const int t0 = (tm >= 4) ? tm - 4 : 0;

    ld_tile(sb, Qhp);
    ld_tile(sb + 8192, Qlp);
    asm volatile("cp.async.commit_group;" ::: "memory");
    kvload(t0, t0 & 1);
    asm volatile("cp.async.wait_group 0;" ::: "memory");
    __syncthreads();

    unsigned qfh[4][4], qfl[4][4];
    const int arow = wm * 16 + (lane & 15);
    const int ahalf = lane >> 4;
#pragma unroll
    for (int s = 0; s < 4; s++) {
        const unsigned off = arow * 128 + (((2 * s + ahalf) ^ (arow & 7)) * 16);
        ldsm4(qfh[s][0], qfh[s][1], qfh[s][2], qfh[s][3], sb + off);
        ldsm4(qfl[s][0], qfl[s][1], qfl[s][2], qfl[s][3], sb + 8192 + off);
    }

    const int brow_b = ((lane >> 4) & 1) * 8 + (lane & 7);
    const int bhalf = (lane >> 3) & 1;
    // trans-ldmatrix lane mapping for V (row-major [t][d])
    const int vrow_b = ((lane >> 3) & 1) * 8 + (lane & 7);   // + 16*s
    const int vgsel = lane >> 4;                             // granule += 0/1

    float m0 = -1e30f, m1 = -1e30f, l0 = 0.f, l1 = 0.f;
    float o[8][4];
#pragma unroll
    for (int nt = 0; nt < 8; nt++)
#pragma unroll
        for (int e = 0; e < 4; e++) o[nt][e] = 0.f;

    const int i0r = qb + wm * 16 + (lane >> 2);
    const int i1r = i0r + 8;
    const int jc = 2 * (lane & 3);

    for (int kt = t0; kt <= tm; kt++) {
        const unsigned kvb = sb + 16384 + (kt & 1) * 32768;
        if (kt < tm) kvload(kt + 1, (kt + 1) & 1);

        // ---- S = Q @ K^T ----
        float sacc[8][4];
#pragma unroll
        for (int nt = 0; nt < 8; nt++)
#pragma unroll
            for (int e = 0; e < 4; e++) sacc[nt][e] = 0.f;

#pragma unroll
        for (int s = 0; s < 4; s++) {
            unsigned kfh[16], kfl[16];
#pragma unroll
            for (int j = 0; j < 4; j++) {
                const int row = brow_b + j * 16;
                const unsigned off = row * 128 + (((2 * s + bhalf) ^ (row & 7)) * 16);
                ldsm4(kfh[4 * j], kfh[4 * j + 1], kfh[4 * j + 2], kfh[4 * j + 3],
                      kvb + off);
                ldsm4(kfl[4 * j], kfl[4 * j + 1], kfl[4 * j + 2], kfl[4 * j + 3],
                      kvb + 8192 + off);
            }
#pragma unroll
            for (int nt = 0; nt < 8; nt++) {
                mma16816(sacc[nt], qfh[s], &kfh[nt * 2]);
                mma16816(sacc[nt], qfh[s], &kfl[nt * 2]);
                mma16816(sacc[nt], qfl[s], &kfh[nt * 2]);
            }
        }

        // ---- mask ----
        const int kb = kt * 64;
        if (kt == tm) {
#pragma unroll
            for (int nt = 0; nt < 8; nt++) {
                const int j0 = kb + nt * 8 + jc;
                if (j0 > i0r)     sacc[nt][0] = -1e30f;
                if (j0 + 1 > i0r) sacc[nt][1] = -1e30f;
                if (j0 > i1r)     sacc[nt][2] = -1e30f;
                if (j0 + 1 > i1r) sacc[nt][3] = -1e30f;
            }
        } else if (kt == tm - 4) {
#pragma unroll
            for (int nt = 0; nt < 8; nt++) {
                const int j0 = kb + nt * 8 + jc;
                if (i0r - j0 >= WINSZ)       sacc[nt][0] = -1e30f;
                if (i0r - (j0 + 1) >= WINSZ) sacc[nt][1] = -1e30f;
                if (i1r - j0 >= WINSZ)       sacc[nt][2] = -1e30f;
                if (i1r - (j0 + 1) >= WINSZ) sacc[nt][3] = -1e30f;
            }
        }

        // ---- online softmax ----
        float rm0 = -1e30f, rm1 = -1e30f;
#pragma unroll
        for (int nt = 0; nt < 8; nt++) {
            rm0 = fmaxf(rm0, fmaxf(sacc[nt][0], sacc[nt][1]));
            rm1 = fmaxf(rm1, fmaxf(sacc[nt][2], sacc[nt][3]));
        }
        rm0 = fmaxf(rm0, __shfl_xor_sync(0xffffffffu, rm0, 1));
        rm0 = fmaxf(rm0, __shfl_xor_sync(0xffffffffu, rm0, 2));
        rm1 = fmaxf(rm1, __shfl_xor_sync(0xffffffffu, rm1, 1));
        rm1 = fmaxf(rm1, __shfl_xor_sync(0xffffffffu, rm1, 2));
        const float mn0 = fmaxf(fmaxf(m0, rm0), -1e20f);
        const float mn1 = fmaxf(fmaxf(m1, rm1), -1e20f);
        const float sc0 = __expf(m0 - mn0);
        const float sc1 = __expf(m1 - mn1);
        m0 = mn0; m1 = mn1;
        float rs0 = 0.f, rs1 = 0.f;
#pragma unroll
        for (int nt = 0; nt < 8; nt++) {
            sacc[nt][0] = __expf(sacc[nt][0] - mn0); rs0 += sacc[nt][0];
            sacc[nt][1] = __expf(sacc[nt][1] - mn0); rs0 += sacc[nt][1];
            sacc[nt][2] = __expf(sacc[nt][2] - mn1); rs1 += sacc[nt][2];
            sacc[nt][3] = __expf(sacc[nt][3] - mn1); rs1 += sacc[nt][3];
        }
        rs0 += __shfl_xor_sync(0xffffffffu, rs0, 1);
        rs0 += __shfl_xor_sync(0xffffffffu, rs0, 2);
        rs1 += __shfl_xor_sync(0xffffffffu, rs1, 1);
        rs1 += __shfl_xor_sync(0xffffffffu, rs1, 2);
        l0 = l0 * sc0 + rs0;
        l1 = l1 * sc1 + rs1;
#pragma unroll
        for (int nt = 0; nt < 8; nt++) {
            o[nt][0] *= sc0; o[nt][1] *= sc0;
            o[nt][2] *= sc1; o[nt][3] *= sc1;
        }

        // ---- O += P @ V (V^T fragments via ldmatrix.trans) ----
#pragma unroll
        for (int s = 0; s < 4; s++) {
            unsigned ph[4], pl[4];
            split2(sacc[2 * s][0], sacc[2 * s][1], ph[0], pl[0]);
            split2(sacc[2 * s][2], sacc[2 * s][3], ph[1], pl[1]);
            split2(sacc[2 * s + 1][0], sacc[2 * s + 1][1], ph[2], pl[2]);
            split2(sacc[2 * s + 1][2], sacc[2 * s + 1][3], ph[3], pl[3]);

            unsigned vfh[16], vfl[16];
            const int vrow = 16 * s + vrow_b;
#pragma unroll
            for (int u = 0; u < 4; u++) {
                const int g = 2 * u + vgsel;
                const unsigned off = vrow * 128 + ((g ^ (vrow & 7)) * 16);
                ldsm4t(vfh[4 * u], vfh[4 * u + 1], vfh[4 * u + 2], vfh[4 * u + 3],
                       kvb + 16384 + off);
                ldsm4t(vfl[4 * u], vfl[4 * u + 1], vfl[4 * u + 2], vfl[4 * u + 3],
                       kvb + 24576 + off);
            }
#pragma unroll
            for (int nt = 0; nt < 8; nt++) {
                mma16816(o[nt], ph, &vfh[nt * 2]);
                mma16816(o[nt], ph, &vfl[nt * 2]);
                mma16816(o[nt], pl, &vfh[nt * 2]);
            }
        }

        if (kt < tm) {
            asm volatile("cp.async.wait_group 0;" ::: "memory");
            __syncthreads();
        }
    }

    // ---- epilogue: y = O / l, split to bf16 hi/lo [B,T,C] ----
    const float inv0 = 1.f / l0;
    const float inv1 = 1.f / l1;
    const size_t orow0 = ((size_t)b * NT + (qb + wm * 16 + (lane >> 2))) * NC + h * HS;
    const size_t orow1 = orow0 + (size_t)8 * NC;
#pragma unroll
    for (int nt = 0; nt < 8; nt++) {
        const int d = nt * 8 + jc;
        unsigned hi, lo;
        split2(o[nt][0] * inv0, o[nt][1] * inv0, hi, lo);
        *(unsigned*)&g_yh[orow0 + d] = hi;
        *(unsigned*)&g_yl[orow0 + d] = lo;
        split2(o[nt][2] * inv1, o[nt][3] * inv1, hi, lo);
        *(unsigned*)&g_yh[orow1 + d] = hi;
        *(unsigned*)&g_yl[orow1 + d] = lo;
    }
}

// ---------------------------------------------------------------------------
extern "C" void kernel_launch(void* const* d_in, const int* in_sizes, int n_in,
                              void* d_out, int out_size)
{
    const float* x      = (const float*)d_in[0];  // [B,T,C]
    const float* W_attn = (const float*)d_in[1];  // [C,3C]
    const float* W_proj = (const float*)d_in[2];  // [C,C]
    float* out = (float*)d_out;                   // [B,T,C]

    cudaFuncSetAttribute((const void*)attn_mma,
                         cudaFuncAttributeMaxDynamicSharedMemorySize, ATTN_SMEM);
    cudaFuncSetAttribute((const void*)hgemm<0>,
                         cudaFuncAttributeMaxDynamicSharedMemorySize, GEMM_SMEM);
    cudaFuncSetAttribute((const void*)hgemm<1>,
                         cudaFuncAttributeMaxDynamicSharedMemorySize, GEMM_SMEM);

    // prep: split x, transpose+split weights
    splitx_kernel<<<MR * NC / 4 / 256, 256>>>((const float4*)x);
    tsplit_kernel<3 * NC, 0><<<dim3(3 * NC / 32, NC / 32), dim3(32, 8)>>>(W_attn);
    tsplit_kernel<NC, 1><<<dim3(NC / 32, NC / 32), dim3(32, 8)>>>(W_proj);

    // 1) QKV projection (HMMA) -> bf16 hi/lo Q/K/V, all row-major
    hgemm<0><<<dim3(3 * NC / 64, MR / 128), 128, GEMM_SMEM>>>(nullptr);

    // 2) HMMA sliding-window attention -> g_yh/g_yl (bf16 split)
    attn_mma<<<dim3(NT / 64, NHD, NB), 128, ATTN_SMEM>>>();

    // 3) output projection (HMMA) -> out
    hgemm<1><<<dim3(NC / 64, MR / 128), 128, GEMM_SMEM>>>(out);
}

// round 14
// speedup vs baseline: 1.1552x; 1.1552x over previous
#include <cuda_runtime.h>
#include <cuda_bf16.h>

#define NB 2
#define NT 2048
#define NC 1024
#define NHD 16
#define HS 64
#define WINSZ 256
#define MR (NB * NT)   // 4096 rows

// ---------------- device-global scratch (allocation-free rule) --------------
__device__ __align__(256) __nv_bfloat16 g_xh[MR * NC], g_xl[MR * NC];
__device__ __align__(256) __nv_bfloat16 g_wah[3 * NC * NC], g_wal[3 * NC * NC]; // W_attn^T
__device__ __align__(256) __nv_bfloat16 g_wph[NC * NC], g_wpl[NC * NC];         // W_proj^T
__device__ __align__(256) __nv_bfloat16 g_yh[MR * NC], g_yl[MR * NC];
// attention operands, bf16 hi/lo, all [b,h,t,d] row-major
__device__ __align__(256) __nv_bfloat16 g_qh[MR * NC], g_ql[MR * NC];   // (pre-scaled 1/8)
__device__ __align__(256) __nv_bfloat16 g_kh[MR * NC], g_kl[MR * NC];
__device__ __align__(256) __nv_bfloat16 g_vh[MR * NC], g_vl[MR * NC];

// ---------------- helpers ---------------------------------------------------
__device__ __forceinline__ unsigned smem_u32(const void* p) {
    unsigned a;
    asm("{ .reg .u64 t; cvta.to.shared.u64 t, %1; cvt.u32.u64 %0, t; }"
        : "=r"(a) : "l"(p));
    return a;
}

__device__ __forceinline__ void ldsm4(unsigned& r0, unsigned& r1, unsigned& r2,
                                      unsigned& r3, unsigned addr) {
    asm volatile("ldmatrix.sync.aligned.m8n8.x4.shared.b16 {%0,%1,%2,%3}, [%4];"
                 : "=r"(r0), "=r"(r1), "=r"(r2), "=r"(r3) : "r"(addr));
}

__device__ __forceinline__ void ldsm4t(unsigned& r0, unsigned& r1, unsigned& r2,
                                       unsigned& r3, unsigned addr) {
    asm volatile("ldmatrix.sync.aligned.m8n8.x4.trans.shared.b16 {%0,%1,%2,%3}, [%4];"
                 : "=r"(r0), "=r"(r1), "=r"(r2), "=r"(r3) : "r"(addr));
}

__device__ __forceinline__ void mma16816(float* d, const unsigned* a, const unsigned* b) {
    asm volatile("mma.sync.aligned.m16n8k16.row.col.f32.bf16.bf16.f32 "
                 "{%0,%1,%2,%3}, {%4,%5,%6,%7}, {%8,%9}, {%0,%1,%2,%3};"
                 : "+f"(d[0]), "+f"(d[1]), "+f"(d[2]), "+f"(d[3])
                 : "r"(a[0]), "r"(a[1]), "r"(a[2]), "r"(a[3]),
                   "r"(b[0]), "r"(b[1]));
}

union Pack4 { __nv_bfloat16 b[4]; uint2 u; };
union PackB2 { __nv_bfloat162 v; unsigned u; };

__device__ __forceinline__ unsigned u32bf(__nv_bfloat162 x) {
    PackB2 p; p.v = x; return p.u;
}

__device__ __forceinline__ void split1(float v, __nv_bfloat16& h, __nv_bfloat16& l) {
    h = __float2bfloat16(v);
    l = __float2bfloat16(v - __bfloat162float(h));
}

__device__ __forceinline__ void split2(float a, float b, unsigned& hi, unsigned& lo) {
    __nv_bfloat162 h = __floats2bfloat162_rn(a, b);
    hi = u32bf(h);
    lo = u32bf(__floats2bfloat162_rn(a - __bfloat162float(h.x),
                                     b - __bfloat162float(h.y)));
}

// ---------------- prep kernels ----------------------------------------------
__global__ __launch_bounds__(256)
void splitx_kernel(const float4* __restrict__ x) {
    int i = blockIdx.x * 256 + threadIdx.x;
    float4 v = x[i];
    Pack4 h, l;
    split1(v.x, h.b[0], l.b[0]);
    split1(v.y, h.b[1], l.b[1]);
    split1(v.z, h.b[2], l.b[2]);
    split1(v.w, h.b[3], l.b[3]);
    ((uint2*)g_xh)[i] = h.u;
    ((uint2*)g_xl)[i] = l.u;
}

template<int NCOLS, int WHICH>
__global__ __launch_bounds__(256)
void tsplit_kernel(const float* __restrict__ W) {
    __shared__ float tile[32][33];
    __nv_bfloat16* Th = WHICH ? g_wph : g_wah;
    __nv_bfloat16* Tl = WHICH ? g_wpl : g_wal;
    const int tx = threadIdx.x, ty = threadIdx.y;
    const int j0 = blockIdx.x * 32;
    const int i0 = blockIdx.y * 32;
#pragma unroll
    for (int r = 0; r < 32; r += 8)
        tile[ty + r][tx] = W[(size_t)(i0 + ty + r) * NCOLS + j0 + tx];
    __syncthreads();
#pragma unroll
    for (int r = 0; r < 32; r += 8) {
        float v = tile[tx][ty + r];
        size_t o = (size_t)(j0 + ty + r) * NC + i0 + tx;
        __nv_bfloat16 h, l;
        split1(v, h, l);
        Th[o] = h;
        Tl[o] = l;
    }
}

// ---------------- split-bf16 HMMA GEMM (R11 config, single barrier) ---------
// CTA tile 128(M) x 64(N), 4 warps along M, warp tile 32x64. K-chunk 64
// (128B SW128 rows). Double-buffered cp.async; 96KB smem -> 2 CTAs/SM.
// ONE __syncthreads per chunk (top-of-loop barrier orders reads-before-
// overwrite across the 2-buffer ring). Register double-buffered fragments.
#define GEMM_TA   16384                          // A tile: 128 rows x 128B
#define GEMM_TBB  8192                           // B tile:  64 rows x 128B
#define GEMM_BUF  (2 * GEMM_TA + 2 * GEMM_TBB)   // 49152
#define GEMM_SMEM (2 * GEMM_BUF)                 // 98304

struct Frag {
    unsigned ah[2][4], al[2][4];
    unsigned bh[16], bl[16];
};

template<int MODE>
__global__ __launch_bounds__(128, 2)
void hgemm(float* __restrict__ Cout) {
    extern __shared__ __align__(1024) char sm[];
    const unsigned sb = smem_u32(sm);
    const int tid = threadIdx.x;
    const int wm = tid >> 5, lane = tid & 31;
    const int col0 = blockIdx.x * 64;
    const int row0 = blockIdx.y * 128;

    const __nv_bfloat16* Ah = MODE ? g_yh : g_xh;
    const __nv_bfloat16* Al = MODE ? g_yl : g_xl;
    const __nv_bfloat16* Bh = MODE ? g_wph : g_wah;
    const __nv_bfloat16* Bl = MODE ? g_wpl : g_wal;

    const char* srcA[2];
    const char* srcB[2];
    srcA[0] = (const char*)Ah + (size_t)row0 * 2048;
    srcA[1] = (const char*)Al + (size_t)row0 * 2048;
    srcB[0] = (const char*)Bh + (size_t)col0 * 2048;
    srcB[1] = (const char*)Bl + (size_t)col0 * 2048;

    auto load_chunk = [&](int c, int b) {
        const unsigned dst0 = sb + b * GEMM_BUF;
#pragma unroll
        for (int t = 0; t < 2; t++) {
#pragma unroll
            for (int i = 0; i < 8; i++) {
                const int unit = tid + i * 128;
                const int r = unit >> 3, cc = unit & 7;
                const unsigned bo = r * 128 + cc * 16;
                const unsigned sw = bo ^ ((bo >> 3) & 0x70);
                const char* s = srcA[t] + (size_t)r * 2048 + c * 128 + cc * 16;
                asm volatile("cp.async.cg.shared.global [%0], [%1], 16;"
                             :: "r"(dst0 + t * GEMM_TA + sw), "l"(s) : "memory");
            }
        }
#pragma unroll
        for (int t = 0; t < 2; t++) {
#pragma unroll
            for (int i = 0; i < 4; i++) {
                const int unit = tid + i * 128;
                const int r = unit >> 3, cc = unit & 7;
                const unsigned bo = r * 128 + cc * 16;
                const unsigned sw = bo ^ ((bo >> 3) & 0x70);
                const char* s = srcB[t] + (size_t)r * 2048 + c * 128 + cc * 16;
                asm volatile("cp.async.cg.shared.global [%0], [%1], 16;"
                             :: "r"(dst0 + 2 * GEMM_TA + t * GEMM_TBB + sw), "l"(s)
                             : "memory");
            }
        }
        asm volatile("cp.async.commit_group;" ::: "memory");
    };

    float acc[2][8][4];
#pragma unroll
    for (int mt = 0; mt < 2; mt++)
#pragma unroll
        for (int nt = 0; nt < 8; nt++)
#pragma unroll
            for (int e = 0; e < 4; e++) acc[mt][nt][e] = 0.f;

    const int arow_b = wm * 32 + (lane & 15);
    const int ahalf = lane >> 4;
    const int brow_b = ((lane >> 4) & 1) * 8 + (lane & 7);
    const int bhalf = (lane >> 3) & 1;

    Frag fr[2];

    auto fetch = [&](int s, Frag& f, unsigned base) {
#pragma unroll
        for (int mt = 0; mt < 2; mt++) {
            const int row = arow_b + mt * 16;
            const unsigned off = row * 128 + (((2 * s + ahalf) ^ (row & 7)) * 16);
            ldsm4(f.ah[mt][0], f.ah[mt][1], f.ah[mt][2], f.ah[mt][3], base + off);
            ldsm4(f.al[mt][0], f.al[mt][1], f.al[mt][2], f.al[mt][3],
                  base + GEMM_TA + off);
        }
#pragma unroll
        for (int j = 0; j < 4; j++) {
            const int row = brow_b + j * 16;
            const unsigned off = row * 128 + (((2 * s + bhalf) ^ (row & 7)) * 16);
            ldsm4(f.bh[4 * j], f.bh[4 * j + 1], f.bh[4 * j + 2], f.bh[4 * j + 3],
                  base + 2 * GEMM_TA + off);
            ldsm4(f.bl[4 * j], f.bl[4 * j + 1], f.bl[4 * j + 2], f.bl[4 * j + 3],
                  base + 2 * GEMM_TA + GEMM_TBB + off);
        }
    };

    auto compute = [&](Frag& f) {
#pragma unroll
        for (int mt = 0; mt < 2; mt++)
#pragma unroll
            for (int nt = 0; nt < 8; nt++) {
                mma16816(acc[mt][nt], f.ah[mt], &f.bh[nt * 2]);
                mma16816(acc[mt][nt], f.ah[mt], &f.bl[nt * 2]);
                mma16816(acc[mt][nt], f.al[mt], &f.bh[nt * 2]);
            }
    };

    load_chunk(0, 0);

    for (int c = 0; c < 16; c++) {
        asm volatile("cp.async.wait_group 0;" ::: "memory");
        __syncthreads();          // single barrier: orders prev-iter reads
                                  // before next load overwrites that buffer
        const unsigned base = sb + (c & 1) * GEMM_BUF;
        fetch(0, fr[0], base);
        if (c < 15) load_chunk(c + 1, (c + 1) & 1);
#pragma unroll
        for (int s = 0; s < 4; s++) {
            if (s < 3) fetch(s + 1, fr[(s + 1) & 1], base);
            compute(fr[s & 1]);
        }
    }

    // -------- epilogue --------
    const int lm = lane >> 2;
    const int ln = (lane & 3) * 2;
#pragma unroll
    for (int mt = 0; mt < 2; mt++) {
        const int m0 = row0 + wm * 32 + mt * 16 + lm;
#pragma unroll
        for (int nt = 0; nt < 8; nt++) {
            const int gn = col0 + nt * 8 + ln;
            if (MODE == 0) {
                const int sect = gn >> 10;
                const int nn = gn & (NC - 1);
                const int hd = nn >> 6, dd = nn & 63;
#pragma unroll
                for (int half = 0; half < 2; half++) {
                    const int m = m0 + half * 8;
                    const int bb = m >> 11;
                    const int tt = m & (NT - 1);
                    float v0 = acc[mt][nt][2 * half];
                    float v1 = acc[mt][nt][2 * half + 1];
                    if (sect == 0) { v0 *= 0.125f; v1 *= 0.125f; }
                    unsigned hi, lo;
                    split2(v0, v1, hi, lo);
                    const size_t off =
                        ((size_t)(bb * NHD + hd) * NT + tt) * HS + dd;
                    if (sect == 0) {
                        *(unsigned*)&g_qh[off] = hi;
                        *(unsigned*)&g_ql[off] = lo;
                    } else if (sect == 1) {
                        *(unsigned*)&g_kh[off] = hi;
                        *(unsigned*)&g_kl[off] = lo;
                    } else {
                        *(unsigned*)&g_vh[off] = hi;
                        *(unsigned*)&g_vl[off] = lo;
                    }
                }
            } else {
#pragma unroll
                for (int half = 0; half < 2; half++) {
                    const int m = m0 + half * 8;
                    float* dst = Cout + (size_t)m * NC + gn;
                    *(float2*)dst = make_float2(acc[mt][nt][2 * half],
                                                acc[mt][nt][2 * half + 1]);
                }
            }
        }
    }
}

// ---------------- HMMA sliding-window flash attention ------------------------
// CTA: 64 queries x 1 head, 128 threads. V row-major; V^T via ldmatrix.trans.
// Smem: Q hi/lo 16KB + double-buffered K/V hi/lo 2x32KB = 80KB.
#define ATTN_SMEM (16384 + 2 * 32768)

__global__ __launch_bounds__(128, 2)
void attn_mma() {
    extern __shared__ __align__(1024) char smraw[];
    const unsigned sb = smem_u32(smraw);
    const int tid = threadIdx.x;
    const int wm = tid >> 5, lane = tid & 31;
    const int qb = blockIdx.x * 64;
    const int h = blockIdx.y, b = blockIdx.z;

    const size_t bh = (size_t)(b * NHD + h);
    const __nv_bfloat16* Qhp = g_qh + (bh * NT + qb) * HS;
    const __nv_bfloat16* Qlp = g_ql + (bh * NT + qb) * HS;
    const __nv_bfloat16* Khp = g_kh + bh * NT * HS;
    const __nv_bfloat16* Klp = g_kl + bh * NT * HS;
    const __nv_bfloat16* Vhp = g_vh + bh * NT * HS;
    const __nv_bfloat16* Vlp = g_vl + bh * NT * HS;

    auto ld_tile = [&](unsigned dst, const __nv_bfloat16* src) {
#pragma unroll
        for (int i = 0; i < 4; i++) {
            const int unit = tid + i * 128;
            const int r = unit >> 3, cc = unit & 7;
            const unsigned d = dst + r * 128 + ((cc ^ (r & 7)) * 16);
            const char* s = (const char*)src + (size_t)r * 128 + cc * 16;
            asm volatile("cp.async.cg.shared.global [%0], [%1], 16;"
                         :: "r"(d), "l"(s) : "memory");
        }
    };

    auto kvload = [&](int kt, int buf) {
        const int kb = kt * 64;
        const unsigned kvb = sb + 16384 + buf * 32768;
        ld_tile(kvb,         Khp + (size_t)kb * HS);
        ld_tile(kvb + 8192,  Klp + (size_t)kb * HS);
        ld_tile(kvb + 16384, Vhp + (size_t)kb * HS);
        ld_tile(kvb + 24576, Vlp + (size_t)kb * HS);
        asm volatile("cp.async.commit_group;" ::: "memory");
    };

    const int tm = qb >> 6;
    const int t0 = (tm >= 4) ? tm - 4 : 0;

    ld_tile(sb, Qhp);
    ld_tile(sb + 8192, Qlp);
    asm volatile("cp.async.commit_group;" ::: "memory");
    kvload(t0, t0 & 1);
    asm volatile("cp.async.wait_group 0;" ::: "memory");
    __syncthreads();

    unsigned qfh[4][4], qfl[4][4];
    const int arow = wm * 16 + (lane & 15);
    const int ahalf = lane >> 4;
#pragma unroll
    for (int s = 0; s < 4; s++) {
        const unsigned off = arow * 128 + (((2 * s + ahalf) ^ (arow & 7)) * 16);
        ldsm4(qfh[s][0], qfh[s][1], qfh[s][2], qfh[s][3], sb + off);
        ldsm4(qfl[s][0], qfl[s][1], qfl[s][2], qfl[s][3], sb + 8192 + off);
    }

    const int brow_b = ((lane >> 4) & 1) * 8 + (lane & 7);
    const int bhalf = (lane >> 3) & 1;
    const int vrow_b = ((lane >> 3) & 1) * 8 + (lane & 7);   // + 16*s
    const int vgsel = lane >> 4;

    float m0 = -1e30f, m1 = -1e30f, l0 = 0.f, l1 = 0.f;
    float o[8][4];
#pragma unroll
    for (int nt = 0; nt < 8; nt++)
#pragma unroll
        for (int e = 0; e < 4; e++) o[nt][e] = 0.f;

    const int i0r = qb + wm * 16 + (lane >> 2);
    const int i1r = i0r + 8;
    const int jc = 2 * (lane & 3);

    for (int kt = t0; kt <= tm; kt++) {
        const unsigned kvb = sb + 16384 + (kt & 1) * 32768;
        if (kt < tm) kvload(kt + 1, (kt + 1) & 1);

        // ---- S = Q @ K^T ----
        float sacc[8][4];
#pragma unroll
        for (int nt = 0; nt < 8; nt++)
#pragma unroll
            for (int e = 0; e < 4; e++) sacc[nt][e] = 0.f;

#pragma unroll
        for (int s = 0; s < 4; s++) {
            unsigned kfh[16], kfl[16];
#pragma unroll
            for (int j = 0; j < 4; j++) {
                const int row = brow_b + j * 16;
                const unsigned off = row * 128 + (((2 * s + bhalf) ^ (row & 7)) * 16);
                ldsm4(kfh[4 * j], kfh[4 * j + 1], kfh[4 * j + 2], kfh[4 * j + 3],
                      kvb + off);
                ldsm4(kfl[4 * j], kfl[4 * j + 1], kfl[4 * j + 2], kfl[4 * j + 3],
                      kvb + 8192 + off);
            }
#pragma unroll
            for (int nt = 0; nt < 8; nt++) {
                mma16816(sacc[nt], qfh[s], &kfh[nt * 2]);
                mma16816(sacc[nt], qfh[s], &kfl[nt * 2]);
                mma16816(sacc[nt], qfl[s], &kfh[nt * 2]);
            }
        }

        // ---- mask ----
        const int kb = kt * 64;
        if (kt == tm) {
#pragma unroll
            for (int nt = 0; nt < 8; nt++) {
                const int j0 = kb + nt * 8 + jc;
                if (j0 > i0r)     sacc[nt][0] = -1e30f;
                if (j0 + 1 > i0r) sacc[nt][1] = -1e30f;
                if (j0 > i1r)     sacc[nt][2] = -1e30f;
                if (j0 + 1 > i1r) sacc[nt][3] = -1e30f;
            }
        } else if (kt == tm - 4) {
#pragma unroll
            for (int nt = 0; nt < 8; nt++) {
                const int j0 = kb + nt * 8 + jc;
                if (i0r - j0 >= WINSZ)       sacc[nt][0] = -1e30f;
                if (i0r - (j0 + 1) >= WINSZ) sacc[nt][1] = -1e30f;
                if (i1r - j0 >= WINSZ)       sacc[nt][2] = -1e30f;
                if (i1r - (j0 + 1) >= WINSZ) sacc[nt][3] = -1e30f;
            }
        }

        // ---- online softmax ----
        float rm0 = -1e30f, rm1 = -1e30f;
#pragma unroll
        for (int nt = 0; nt < 8; nt++) {
            rm0 = fmaxf(rm0, fmaxf(sacc[nt][0], sacc[nt][1]));
            rm1 = fmaxf(rm1, fmaxf(sacc[nt][2], sacc[nt][3]));
        }
        rm0 = fmaxf(rm0, __shfl_xor_sync(0xffffffffu, rm0, 1));
        rm0 = fmaxf(rm0, __shfl_xor_sync(0xffffffffu, rm0, 2));
        rm1 = fmaxf(rm1, __shfl_xor_sync(0xffffffffu, rm1, 1));
        rm1 = fmaxf(rm1, __shfl_xor_sync(0xffffffffu, rm1, 2));
        const float mn0 = fmaxf(fmaxf(m0, rm0), -1e20f);
        const float mn1 = fmaxf(fmaxf(m1, rm1), -1e20f);
        const float sc0 = __expf(m0 - mn0);
        const float sc1 = __expf(m1 - mn1);
        m0 = mn0; m1 = mn1;
        float rs0 = 0.f, rs1 = 0.f;
#pragma unroll
        for (int nt = 0; nt < 8; nt++) {
            sacc[nt][0] = __expf(sacc[nt][0] - mn0); rs0 += sacc[nt][0];
            sacc[nt][1] = __expf(sacc[nt][1] - mn0); rs0 += sacc[nt][1];
            sacc[nt][2] = __expf(sacc[nt][2] - mn1); rs1 += sacc[nt][2];
            sacc[nt][3] = __expf(sacc[nt][3] - mn1); rs1 += sacc[nt][3];
        }
        rs0 += __shfl_xor_sync(0xffffffffu, rs0, 1);
        rs0 += __shfl_xor_sync(0xffffffffu, rs0, 2);
        rs1 += __shfl_xor_sync(0xffffffffu, rs1, 1);
        rs1 += __shfl_xor_sync(0xffffffffu, rs1, 2);
        l0 = l0 * sc0 + rs0;
        l1 = l1 * sc1 + rs1;
#pragma unroll
        for (int nt = 0; nt < 8; nt++) {
            o[nt][0] *= sc0; o[nt][1] *= sc0;
            o[nt][2] *= sc1; o[nt][3] *= sc1;
        }

        // ---- O += P @ V (V^T fragments via ldmatrix.trans) ----
#pragma unroll
        for (int s = 0; s < 4; s++) {
            unsigned ph[4], pl[4];
            split2(sacc[2 * s][0], sacc[2 * s][1], ph[0], pl[0]);
            split2(sacc[2 * s][2], sacc[2 * s][3], ph[1], pl[1]);
            split2(sacc[2 * s + 1][0], sacc[2 * s + 1][1], ph[2], pl[2]);
            split2(sacc[2 * s + 1][2], sacc[2 * s + 1][3], ph[3], pl[3]);

            unsigned vfh[16], vfl[16];
            const int vrow = 16 * s + vrow_b;
#pragma unroll
            for (int u = 0; u < 4; u++) {
                const int g = 2 * u + vgsel;
                const unsigned off = vrow * 128 + ((g ^ (vrow & 7)) * 16);
                ldsm4t(vfh[4 * u], vfh[4 * u + 1], vfh[4 * u + 2], vfh[4 * u + 3],
                       kvb + 16384 + off);
                ldsm4t(vfl[4 * u], vfl[4 * u + 1], vfl[4 * u + 2], vfl[4 * u + 3],
                       kvb + 24576 + off);
            }
#pragma unroll
            for (int nt = 0; nt < 8; nt++) {
                mma16816(o[nt], ph, &vfh[nt * 2]);
                mma16816(o[nt], ph, &vfl[nt * 2]);
                mma16816(o[nt], pl, &vfh[nt * 2]);
            }
        }

        if (kt < tm) {
            asm volatile("cp.async.wait_group 0;" ::: "memory");
            __syncthreads();
        }
    }

    // ---- epilogue: y = O / l, split to bf16 hi/lo [B,T,C] ----
    const float inv0 = 1.f / l0;
    const float inv1 = 1.f / l1;
    const size_t orow0 = ((size_t)b * NT + (qb + wm * 16 + (lane >> 2))) * NC + h * HS;
    const size_t orow1 = orow0 + (size_t)8 * NC;
#pragma unroll
    for (int nt = 0; nt < 8; nt++) {
        const int d = nt * 8 + jc;
        unsigned hi, lo;
        split2(o[nt][0] * inv0, o[nt][1] * inv0, hi, lo);
        *(unsigned*)&g_yh[orow0 + d] = hi;
        *(unsigned*)&g_yl[orow0 + d] = lo;
        split2(o[nt][2] * inv1, o[nt][3] * inv1, hi, lo);
        *(unsigned*)&g_yh[orow1 + d] = hi;
        *(unsigned*)&g_yl[orow1 + d] = lo;
    }
}

// ---------------------------------------------------------------------------
extern "C" void kernel_launch(void* const* d_in, const int* in_sizes, int n_in,
                              void* d_out, int out_size)
{
    const float* x      = (const float*)d_in[0];  // [B,T,C]
    const float* W_attn = (const float*)d_in[1];  // [C,3C]
    const float* W_proj = (const float*)d_in[2];  // [C,C]
    float* out = (float*)d_out;                   // [B,T,C]

    cudaFuncSetAttribute((const void*)attn_mma,
                         cudaFuncAttributeMaxDynamicSharedMemorySize, ATTN_SMEM);
    cudaFuncSetAttribute((const void*)hgemm<0>,
                         cudaFuncAttributeMaxDynamicSharedMemorySize, GEMM_SMEM);
    cudaFuncSetAttribute((const void*)hgemm<1>,
                         cudaFuncAttributeMaxDynamicSharedMemorySize, GEMM_SMEM);

    // prep: split x, transpose+split weights
    splitx_kernel<<<MR * NC / 4 / 256, 256>>>((const float4*)x);
    tsplit_kernel<3 * NC, 0><<<dim3(3 * NC / 32, NC / 32), dim3(32, 8)>>>(W_attn);
    tsplit_kernel<NC, 1><<<dim3(NC / 32, NC / 32), dim3(32, 8)>>>(W_proj);

    // 1) QKV projection (HMMA) -> bf16 hi/lo Q/K/V, all row-major
    hgemm<0><<<dim3(3 * NC / 64, MR / 128), 128, GEMM_SMEM>>>(nullptr);

    // 2) HMMA sliding-window attention -> g_yh/g_yl (bf16 split)
    attn_mma<<<dim3(NT / 64, NHD, NB), 128, ATTN_SMEM>>>();

    // 3) output projection (HMMA) -> out
    hgemm<1><<<dim3(NC / 64, MR / 128), 128, GEMM_SMEM>>>(out);
}